// round 2
// baseline (speedup 1.0000x reference)
#include <cuda_runtime.h>
#include <math.h>

// ---------------- problem constants ----------------
#define V0v 1958
#define V1v 1430
#define V2v 131
#define KG_LEAFv 3519
#define N_ENTv 96481
#define Cv 128
#define E_KGv 500000
#define NNZv 200000
#define MROWSv 3522            // 1958 diag + 1430 proc + 134 med rows
#define LDEv 3520              // leading dim of E (padded to /32)
#define Bv 16
#define Sv 8
#define NDv 40
#define NPv 30
#define NMv 30

// ---------------- device scratch (static globals: no runtime allocation) ----
__device__ __align__(16) float g_ent[N_ENTv * Cv];      // entity_emb (current)
__device__ __align__(16) float g_entagg[N_ENTv * Cv];   // edge scatter target
__device__ __align__(16) float g_usr[KG_LEAFv * Cv];    // user_emb (current)
__device__ __align__(16) float g_usragg[KG_LEAFv * Cv];
__device__ __align__(16) float g_usrres[KG_LEAFv * Cv]; // leaf_intent accumulator
__device__ __align__(16) float g_dw[8 * Cv];            // disen_weight (8,128)
__device__ __align__(16) float g_X[MROWSv * Cv];        // distinct code embeddings
__device__ __align__(16) float g_IK[MROWSv * Cv];       // per-code ik vectors
__device__ __align__(16) float g_E[MROWSv * LDEv];      // exp(logits) ~49.6MB
__device__ __align__(16) float g_P[MROWSv * Cv];        // normalized intent per code
__device__ float g_s[MROWSv];                           // row sums of E
__device__ __align__(16) float g_Tun[MROWSv * Cv];      // tanh table, unmasked
__device__ __align__(16) float g_Tma[MROWSv * Cv];      // tanh table, masked (int=0)

__device__ __forceinline__ void atomAdd4(float4* addr, float4 v) {
#if defined(__CUDA_ARCH__) && (__CUDA_ARCH__ >= 900)
    atomicAdd(addr, v);
#else
    float* a = (float*)addr;
    atomicAdd(a + 0, v.x); atomicAdd(a + 1, v.y);
    atomicAdd(a + 2, v.z); atomicAdd(a + 3, v.w);
#endif
}

// ---------------- init: copy embeddings, zero accumulators ----------------
__global__ void k_init(const float* __restrict__ all_embed) {
    int i = blockIdx.x * blockDim.x + threadIdx.x;
    if (i < KG_LEAFv * Cv) {
        float v = all_embed[i];
        g_usr[i] = v; g_usrres[i] = v; g_usragg[i] = 0.f;
    }
    if (i < N_ENTv * Cv) {
        g_ent[i] = all_embed[KG_LEAFv * Cv + i];
        g_entagg[i] = 0.f;
    }
    if (i < MROWSv) g_s[i] = 0.f;
}

// ---------------- disen_weight = softmax(disen_att, -1) @ kg_weight ----------
__global__ void k_disen(const float* __restrict__ att, const float* __restrict__ kw) {
    __shared__ float p[8 * 49];
    int t = threadIdx.x;
    if (t < 8) {
        float m = -1e30f;
        for (int r = 0; r < 49; r++) m = fmaxf(m, att[t * 49 + r]);
        float s = 0.f;
        for (int r = 0; r < 49; r++) { float e = expf(att[t * 49 + r] - m); p[t * 49 + r] = e; s += e; }
        float inv = 1.f / s;
        for (int r = 0; r < 49; r++) p[t * 49 + r] *= inv;
    }
    __syncthreads();
    // t = output channel 0..127
    for (int k = 0; k < 8; k++) {
        float a = 0.f;
        for (int r = 0; r < 49; r++) a += p[k * 49 + r] * kw[r * Cv + t];
        g_dw[k * Cv + t] = a;
    }
}

// ---------------- GNN hop: edge scatter (warp per edge, float4 lanes) --------
__global__ void __launch_bounds__(256) k_edges(
        const int* __restrict__ eh, const int* __restrict__ et,
        const int* __restrict__ ety, const float* __restrict__ kw) {
    int gid = blockIdx.x * blockDim.x + threadIdx.x;
    int e = gid >> 5, lane = gid & 31;
    if (e >= E_KGv) return;
    int tl = et[e], ty = ety[e], h = eh[e];
    float4 v = ((const float4*)g_ent)[tl * 32 + lane];
    float4 w = ((const float4*)kw)[(ty - 1) * 32 + lane];
    v.x *= w.x; v.y *= w.y; v.z *= w.z; v.w *= w.w;
    atomAdd4(((float4*)g_entagg) + h * 32 + lane, v);
}

// ---------------- GNN hop: interaction scatter -------------------------------
__global__ void __launch_bounds__(256) k_inter(
        const int* __restrict__ ir, const int* __restrict__ ic,
        const float* __restrict__ iv) {
    int gid = blockIdx.x * blockDim.x + threadIdx.x;
    int nz = gid >> 5, lane = gid & 31;
    if (nz >= NNZv) return;
    int r = ir[nz], cI = ic[nz];
    float v = iv[nz];
    float4 x = ((const float4*)g_ent)[cI * 32 + lane];
    x.x *= v; x.y *= v; x.z *= v; x.w *= v;
    atomAdd4(((float4*)g_usragg) + r * 32 + lane, x);
}

// ---------------- GNN hop: entity update (l2norm; degree cancels) ------------
__global__ void __launch_bounds__(256) k_entup() {
    int gid = blockIdx.x * blockDim.x + threadIdx.x;
    int r = gid >> 5, lane = gid & 31;
    if (r >= N_ENTv) return;
    float4* agg4 = (float4*)g_entagg;
    float4 x = agg4[r * 32 + lane];
    float ss = x.x * x.x + x.y * x.y + x.z * x.z + x.w * x.w;
    #pragma unroll
    for (int m = 16; m >= 1; m >>= 1) ss += __shfl_xor_sync(0xffffffffu, ss, m);
    float inv = 1.f / fmaxf(sqrtf(ss), 1e-12f);
    x.x *= inv; x.y *= inv; x.z *= inv; x.w *= inv;
    ((float4*)g_ent)[r * 32 + lane] = x;
    agg4[r * 32 + lane] = make_float4(0.f, 0.f, 0.f, 0.f);
}

// ---------------- GNN hop: user/leaf update ----------------------------------
__global__ void __launch_bounds__(256) k_usrup(const float* __restrict__ latent) {
    int gid = blockIdx.x * blockDim.x + threadIdx.x;
    int r = gid >> 5, lane = gid & 31;
    if (r >= KG_LEAFv) return;
    float4* usr4 = (float4*)g_usr;
    float4* agg4 = (float4*)g_usragg;
    float4* res4 = (float4*)g_usrres;
    const float4* lat4 = (const float4*)latent;
    const float4* dw4 = (const float4*)g_dw;

    float4 u = usr4[r * 32 + lane];   // OLD user_emb for score
    float l[8];
    #pragma unroll
    for (int k = 0; k < 8; k++) {
        float4 lt = lat4[k * 32 + lane];
        float p = u.x * lt.x + u.y * lt.y + u.z * lt.z + u.w * lt.w;
        #pragma unroll
        for (int m = 16; m >= 1; m >>= 1) p += __shfl_xor_sync(0xffffffffu, p, m);
        l[k] = p;
    }
    float mx = l[0];
    #pragma unroll
    for (int k = 1; k < 8; k++) mx = fmaxf(mx, l[k]);
    float s = 0.f;
    #pragma unroll
    for (int k = 0; k < 8; k++) { l[k] = expf(l[k] - mx); s += l[k]; }
    float invs = 1.f / s;
    float4 g = make_float4(0.f, 0.f, 0.f, 0.f);
    #pragma unroll
    for (int k = 0; k < 8; k++) {
        float sc = l[k] * invs;
        float4 d = dw4[k * 32 + lane];
        g.x += sc * d.x; g.y += sc * d.y; g.z += sc * d.z; g.w += sc * d.w;
    }
    float4 a = agg4[r * 32 + lane];
    a.x *= (1.f + g.x); a.y *= (1.f + g.y); a.z *= (1.f + g.z); a.w *= (1.f + g.w);
    float ss = a.x * a.x + a.y * a.y + a.z * a.z + a.w * a.w;
    #pragma unroll
    for (int m = 16; m >= 1; m >>= 1) ss += __shfl_xor_sync(0xffffffffu, ss, m);
    float inv = 1.f / fmaxf(sqrtf(ss), 1e-12f);
    a.x *= inv; a.y *= inv; a.z *= inv; a.w *= inv;
    usr4[r * 32 + lane] = a;
    float4 rr = res4[r * 32 + lane];
    rr.x += a.x; rr.y += a.y; rr.z += a.z; rr.w += a.w;
    res4[r * 32 + lane] = rr;
    agg4[r * 32 + lane] = make_float4(0.f, 0.f, 0.f, 0.f);
}

// ---------------- build distinct-code matrices X and IK ----------------------
__global__ void k_buildX(const float* __restrict__ dt, const float* __restrict__ pt,
                         const float* __restrict__ mt) {
    int i = blockIdx.x * blockDim.x + threadIdx.x;
    if (i >= MROWSv * Cv) return;
    int row = i >> 7, c = i & 127;
    float x;
    if (row < V0v)             x = dt[row * Cv + c];
    else if (row < V0v + V1v)  x = pt[(row - V0v) * Cv + c];
    else                       x = mt[(row - V0v - V1v) * Cv + c];
    g_X[i] = x;
    g_IK[i] = (row < KG_LEAFv) ? g_usrres[i] : 0.f;
}

// ---------------- GEMM A: E = exp(X @ L^T), g_s = rowsum(E) ------------------
// 128x128 tiles, 256 threads, 8x8 microtile, K=128 in chunks of 32.
__global__ void __launch_bounds__(256) kA_logits() {
    __shared__ float Xs[32][132];
    __shared__ float Ls[32][132];
    const int rowbase = blockIdx.x * 128;
    const int colbase = blockIdx.y * 128;
    const int t = threadIdx.x;
    const int tx = t & 15, ty = t >> 4;
    const int m0 = ty * 8, n0 = tx * 8;
    float acc[8][8];
    #pragma unroll
    for (int i = 0; i < 8; i++)
        #pragma unroll
        for (int j = 0; j < 8; j++) acc[i][j] = 0.f;

    for (int kc = 0; kc < 4; kc++) {
        #pragma unroll
        for (int it = 0; it < 4; it++) {
            int lin = t + it * 256;
            int row = lin >> 3, q = lin & 7;
            int gr = rowbase + row;
            float4 v = make_float4(0.f, 0.f, 0.f, 0.f);
            if (gr < MROWSv) v = *(const float4*)&g_X[gr * Cv + kc * 32 + q * 4];
            Xs[q * 4 + 0][row] = v.x; Xs[q * 4 + 1][row] = v.y;
            Xs[q * 4 + 2][row] = v.z; Xs[q * 4 + 3][row] = v.w;
            int gc = colbase + row;
            float4 w = make_float4(0.f, 0.f, 0.f, 0.f);
            if (gc < KG_LEAFv) w = *(const float4*)&g_usrres[gc * Cv + kc * 32 + q * 4];
            Ls[q * 4 + 0][row] = w.x; Ls[q * 4 + 1][row] = w.y;
            Ls[q * 4 + 2][row] = w.z; Ls[q * 4 + 3][row] = w.w;
        }
        __syncthreads();
        #pragma unroll
        for (int kk = 0; kk < 32; kk++) {
            float4 a0 = *(const float4*)&Xs[kk][m0];
            float4 a1 = *(const float4*)&Xs[kk][m0 + 4];
            float4 b0 = *(const float4*)&Ls[kk][n0];
            float4 b1 = *(const float4*)&Ls[kk][n0 + 4];
            float a[8] = {a0.x, a0.y, a0.z, a0.w, a1.x, a1.y, a1.z, a1.w};
            float b[8] = {b0.x, b0.y, b0.z, b0.w, b1.x, b1.y, b1.z, b1.w};
            #pragma unroll
            for (int i = 0; i < 8; i++)
                #pragma unroll
                for (int j = 0; j < 8; j++) acc[i][j] += a[i] * b[j];
        }
        __syncthreads();
    }
    #pragma unroll
    for (int i = 0; i < 8; i++) {
        int row = rowbase + m0 + i;
        float rs = 0.f;
        if (row < MROWSv) {
            #pragma unroll
            for (int j = 0; j < 8; j++) {
                int col = colbase + n0 + j;
                if (col < KG_LEAFv) {
                    float e = expf(acc[i][j]);
                    g_E[row * LDEv + col] = e;
                    rs += e;
                }
            }
        }
        rs += __shfl_xor_sync(0xffffffffu, rs, 1);
        rs += __shfl_xor_sync(0xffffffffu, rs, 2);
        rs += __shfl_xor_sync(0xffffffffu, rs, 4);
        rs += __shfl_xor_sync(0xffffffffu, rs, 8);
        if (tx == 0 && row < MROWSv) atomicAdd(&g_s[row], rs);
    }
}

// ---------------- GEMM B: P = (E @ L) / rowsum -------------------------------
// M=3522 in 128-row tiles (grid 28), N=128, K=3519 in chunks of 32.
__global__ void __launch_bounds__(256) kB_P() {
    __shared__ float Es[32][132];
    __shared__ float Ls[32][132];
    const int rowbase = blockIdx.x * 128;
    const int t = threadIdx.x;
    const int tx = t & 15, ty = t >> 4;
    const int m0 = ty * 8, n0 = tx * 8;
    float acc[8][8];
    #pragma unroll
    for (int i = 0; i < 8; i++)
        #pragma unroll
        for (int j = 0; j < 8; j++) acc[i][j] = 0.f;

    for (int ch = 0; ch < 110; ch++) {
        int j0 = ch * 32;
        #pragma unroll
        for (int it = 0; it < 4; it++) {
            int lin = t + it * 256;
            int row = lin >> 3, q = lin & 7;
            int gr = rowbase + row;
            int k = j0 + q * 4;
            float4 v = make_float4(0.f, 0.f, 0.f, 0.f);
            if (gr < MROWSv) {
                if (k + 3 < KG_LEAFv) {
                    v = *(const float4*)&g_E[gr * LDEv + k];
                } else {
                    float* vp = &v.x;
                    #pragma unroll
                    for (int j = 0; j < 4; j++)
                        if (k + j < KG_LEAFv) vp[j] = g_E[gr * LDEv + k + j];
                }
            }
            Es[q * 4 + 0][row] = v.x; Es[q * 4 + 1][row] = v.y;
            Es[q * 4 + 2][row] = v.z; Es[q * 4 + 3][row] = v.w;
        }
        #pragma unroll
        for (int it = 0; it < 4; it++) {
            int lin = t + it * 256;
            int kr = lin >> 5, q = lin & 31;
            int gk = j0 + kr;
            float4 v = make_float4(0.f, 0.f, 0.f, 0.f);
            if (gk < KG_LEAFv) v = *(const float4*)&g_usrres[gk * Cv + q * 4];
            *(float4*)&Ls[kr][q * 4] = v;
        }
        __syncthreads();
        #pragma unroll
        for (int kk = 0; kk < 32; kk++) {
            float4 a0 = *(const float4*)&Es[kk][m0];
            float4 a1 = *(const float4*)&Es[kk][m0 + 4];
            float4 b0 = *(const float4*)&Ls[kk][n0];
            float4 b1 = *(const float4*)&Ls[kk][n0 + 4];
            float a[8] = {a0.x, a0.y, a0.z, a0.w, a1.x, a1.y, a1.z, a1.w};
            float b[8] = {b0.x, b0.y, b0.z, b0.w, b1.x, b1.y, b1.z, b1.w};
            #pragma unroll
            for (int i = 0; i < 8; i++)
                #pragma unroll
                for (int j = 0; j < 8; j++) acc[i][j] += a[i] * b[j];
        }
        __syncthreads();
    }
    #pragma unroll
    for (int i = 0; i < 8; i++) {
        int row = rowbase + m0 + i;
        if (row < MROWSv) {
            float inv = 1.f / g_s[row];
            #pragma unroll
            for (int j = 0; j < 8; j++) g_P[row * Cv + n0 + j] = acc[i][j] * inv;
        }
    }
}

// ---------------- tanh tables: one block per code row ------------------------
__global__ void __launch_bounds__(128) k_tanh(
        const float* __restrict__ dw_, const float* __restrict__ db_,
        const float* __restrict__ pw_, const float* __restrict__ pb_,
        const float* __restrict__ mw_, const float* __restrict__ mb_) {
    int row = blockIdx.x;
    int c = threadIdx.x;
    __shared__ float sIn[256];
    sIn[c] = g_P[row * Cv + c];
    sIn[128 + c] = g_IK[row * Cv + c];
    __syncthreads();
    const float* W; const float* b;
    if (row < V0v)            { W = dw_; b = db_; }
    else if (row < V0v + V1v) { W = pw_; b = pb_; }
    else                      { W = mw_; b = mb_; }
    float au = 0.f, am = 0.f;
    #pragma unroll 4
    for (int r = 0; r < 128; r++) au += sIn[r] * W[r * Cv + c];
    #pragma unroll 4
    for (int r = 128; r < 256; r++) {
        float v = sIn[r] * W[r * Cv + c];
        au += v; am += v;
    }
    g_Tun[row * Cv + c] = tanhf(au + b[c]);
    g_Tma[row * Cv + c] = tanhf(am + b[c]);
}

// ---------------- final: per-(b,s) gather-sum + 384->128 matvec + tanh -------
__global__ void __launch_bounds__(128) k_final(
        const int* __restrict__ dis, const int* __restrict__ prc,
        const int* __restrict__ med,
        const float* __restrict__ dm, const float* __restrict__ pm,
        const float* __restrict__ mm,
        const float* __restrict__ cw, const float* __restrict__ cb,
        float* __restrict__ out) {
    int bs = blockIdx.x;           // b*S + s, 0..127
    int s = bs & (Sv - 1);
    int c = threadIdx.x;
    __shared__ float cat[384];
    float ad = 0.f, ap = 0.f, am = 0.f;
    for (int n = 0; n < NDv; n++) {
        int idx = dis[bs * NDv + n];
        bool msk = dm[bs * NDv + n] != 0.f;
        ad += msk ? g_Tma[idx * Cv + c] : g_Tun[idx * Cv + c];
    }
    for (int n = 0; n < NPv; n++) {
        int idx = prc[bs * NPv + n] + V0v;
        bool msk = pm[bs * NPv + n] != 0.f;
        ap += msk ? g_Tma[idx * Cv + c] : g_Tun[idx * Cv + c];
    }
    if (s == 0) {
        am = (float)NMv * g_Tma[(MROWSv - 1) * Cv + c];  // code 133, masked
    } else {
        int pb = bs - 1;
        for (int n = 0; n < NMv; n++) {
            int idx = med[pb * NMv + n] + (V0v + V1v);
            bool msk = mm[pb * NMv + n] != 0.f;
            am += msk ? g_Tma[idx * Cv + c] : g_Tun[idx * Cv + c];
        }
    }
    cat[c] = ad; cat[128 + c] = ap; cat[256 + c] = am;
    __syncthreads();
    float acc = cb[c];
    #pragma unroll 4
    for (int r = 0; r < 384; r++) acc += cat[r] * cw[r * Cv + c];
    out[bs * Cv + c] = tanhf(acc);
}

// ---------------- launch -----------------------------------------------------
extern "C" void kernel_launch(void* const* d_in, const int* in_sizes, int n_in,
                              void* d_out, int out_size) {
    const int*   diseases    = (const int*)  d_in[0];
    const int*   procedures  = (const int*)  d_in[1];
    const int*   medications = (const int*)  d_in[2];
    const float* d_mask      = (const float*)d_in[3];
    const float* p_mask      = (const float*)d_in[4];
    const float* m_mask      = (const float*)d_in[5];
    const int*   edge_head   = (const int*)  d_in[6];
    const int*   edge_tail   = (const int*)  d_in[7];
    const int*   edge_type   = (const int*)  d_in[8];
    const int*   inter_rows  = (const int*)  d_in[9];
    const int*   inter_cols  = (const int*)  d_in[10];
    const float* inter_vals  = (const float*)d_in[11];
    const float* all_embed   = (const float*)d_in[12];
    const float* latent_emb  = (const float*)d_in[13];
    const float* kg_weight   = (const float*)d_in[14];
    const float* disen_att   = (const float*)d_in[15];
    const float* diag_table  = (const float*)d_in[16];
    const float* proc_table  = (const float*)d_in[17];
    const float* med_table   = (const float*)d_in[18];
    const float* diag_w      = (const float*)d_in[19];
    const float* diag_b      = (const float*)d_in[20];
    const float* proc_w      = (const float*)d_in[21];
    const float* proc_b      = (const float*)d_in[22];
    const float* med_w       = (const float*)d_in[23];
    const float* med_b       = (const float*)d_in[24];
    const float* curt_w      = (const float*)d_in[25];
    const float* curt_b      = (const float*)d_in[26];
    float* out = (float*)d_out;

    k_init<<<(N_ENTv * Cv + 255) / 256, 256>>>(all_embed);
    k_disen<<<1, 128>>>(disen_att, kg_weight);

    for (int h = 0; h < 3; h++) {
        k_edges<<<(E_KGv * 32 + 255) / 256, 256>>>(edge_head, edge_tail, edge_type, kg_weight);
        k_inter<<<(NNZv * 32 + 255) / 256, 256>>>(inter_rows, inter_cols, inter_vals);
        k_entup<<<(N_ENTv * 32 + 255) / 256, 256>>>();
        k_usrup<<<(KG_LEAFv * 32 + 255) / 256, 256>>>(latent_emb);
    }

    k_buildX<<<(MROWSv * Cv + 255) / 256, 256>>>(diag_table, proc_table, med_table);

    dim3 gA(28, 28);
    kA_logits<<<gA, 256>>>();
    kB_P<<<28, 256>>>();

    k_tanh<<<MROWSv, 128>>>(diag_w, diag_b, proc_w, proc_b, med_w, med_b);
    k_final<<<Bv * Sv, 128>>>(diseases, procedures, medications,
                              d_mask, p_mask, m_mask, curt_w, curt_b, out);
}

// round 4
// speedup vs baseline: 1.6563x; 1.6563x over previous
#include <cuda_runtime.h>
#include <math.h>

// ---------------- problem constants ----------------
#define V0v 1958
#define V1v 1430
#define V2v 131
#define KG_LEAFv 3519
#define N_ENTv 96481
#define Cv 128
#define E_KGv 500000
#define NNZv 200000
#define MROWSv 3522            // 1958 diag + 1430 proc + 134 med rows
#define LDEv 3520              // leading dim of E (padded to /32)
#define Bv 16
#define Sv 8
#define NDv 40
#define NPv 30
#define NMv 30
#define KSPLITv 10             // split-K factor for GEMM B

// ---------------- device scratch (static globals: no runtime allocation) ----
// NOTE: .bss is zero-initialized at module load. g_entagg / g_usragg are
// restored to zero by k_update every hop, so they are never re-zeroed here.
__device__ __align__(16) float g_ent[N_ENTv * Cv];      // entity_emb (current)
__device__ __align__(16) float g_entagg[N_ENTv * Cv];   // edge scatter target
__device__ __align__(16) float g_usr[KG_LEAFv * Cv];    // user_emb (current)
__device__ __align__(16) float g_usragg[KG_LEAFv * Cv];
__device__ __align__(16) float g_usrres[KG_LEAFv * Cv]; // leaf_intent accumulator
__device__ __align__(16) float g_dw[8 * Cv];            // disen_weight (8,128)
__device__ __align__(16) float g_X[MROWSv * Cv];        // distinct code embeddings
__device__ __align__(16) float g_IK[MROWSv * Cv];       // per-code ik vectors
__device__ __align__(16) float g_E[MROWSv * LDEv];      // exp(logits) ~49.6MB
__device__ __align__(16) float g_P[MROWSv * Cv];        // E@L partial sums (unnormalized)
__device__ float g_s[MROWSv];                           // row sums of E
__device__ __align__(16) float g_Tun[MROWSv * Cv];      // tanh table, unmasked
__device__ __align__(16) float g_Tma[MROWSv * Cv];      // tanh table, masked (int=0)

__device__ __forceinline__ void atomAdd4(float4* addr, float4 v) {
#if defined(__CUDA_ARCH__) && (__CUDA_ARCH__ >= 900)
    atomicAdd(addr, v);
#else
    float* a = (float*)addr;
    atomicAdd(a + 0, v.x); atomicAdd(a + 1, v.y);
    atomicAdd(a + 2, v.z); atomicAdd(a + 3, v.w);
#endif
}

// ---------------- init: copy embeddings (agg buffers stay zero by invariant) -
__global__ void k_init(const float* __restrict__ all_embed) {
    int i = blockIdx.x * blockDim.x + threadIdx.x;
    if (i < KG_LEAFv * Cv) {
        float v = all_embed[i];
        g_usr[i] = v; g_usrres[i] = v;
    }
    if (i < N_ENTv * Cv) {
        g_ent[i] = all_embed[KG_LEAFv * Cv + i];
    }
    if (i < MROWSv) g_s[i] = 0.f;
}

// ---------------- disen_weight = softmax(disen_att, -1) @ kg_weight ----------
__global__ void k_disen(const float* __restrict__ att, const float* __restrict__ kw) {
    __shared__ float p[8 * 49];
    int t = threadIdx.x;
    if (t < 8) {
        float m = -1e30f;
        for (int r = 0; r < 49; r++) m = fmaxf(m, att[t * 49 + r]);
        float s = 0.f;
        for (int r = 0; r < 49; r++) { float e = __expf(att[t * 49 + r] - m); p[t * 49 + r] = e; s += e; }
        float inv = 1.f / s;
        for (int r = 0; r < 49; r++) p[t * 49 + r] *= inv;
    }
    __syncthreads();
    for (int k = 0; k < 8; k++) {
        float a = 0.f;
        for (int r = 0; r < 49; r++) a += p[k * 49 + r] * kw[r * Cv + t];
        g_dw[k * Cv + t] = a;
    }
}

// ---------------- GNN hop: merged edge + interaction scatter -----------------
// warp per work item; items [0, E_KG) = edges, [E_KG, E_KG+NNZ) = inter nnz.
__global__ void __launch_bounds__(256) k_scatter(
        const int* __restrict__ eh, const int* __restrict__ et,
        const int* __restrict__ ety, const float* __restrict__ kw,
        const int* __restrict__ ir, const int* __restrict__ ic,
        const float* __restrict__ iv) {
    int gid = blockIdx.x * blockDim.x + threadIdx.x;
    int w = gid >> 5, lane = gid & 31;
    if (w < E_KGv) {
        int tl = et[w], ty = ety[w], h = eh[w];
        float4 v = ((const float4*)g_ent)[tl * 32 + lane];
        float4 ww = ((const float4*)kw)[(ty - 1) * 32 + lane];
        v.x *= ww.x; v.y *= ww.y; v.z *= ww.z; v.w *= ww.w;
        atomAdd4(((float4*)g_entagg) + h * 32 + lane, v);
    } else {
        int nz = w - E_KGv;
        if (nz >= NNZv) return;
        int r = ir[nz], cI = ic[nz];
        float v = iv[nz];
        float4 x = ((const float4*)g_ent)[cI * 32 + lane];
        x.x *= v; x.y *= v; x.z *= v; x.w *= v;
        atomAdd4(((float4*)g_usragg) + r * 32 + lane, x);
    }
}

// ---------------- GNN hop: merged entity + user update -----------------------
// warp per row; rows [0, N_ENT) = entity, [N_ENT, N_ENT+KG_LEAF) = user.
__global__ void __launch_bounds__(256) k_update(const float* __restrict__ latent) {
    int gid = blockIdx.x * blockDim.x + threadIdx.x;
    int w = gid >> 5, lane = gid & 31;
    if (w < N_ENTv) {
        float4* agg4 = (float4*)g_entagg;
        float4 x = agg4[w * 32 + lane];
        float ss = x.x * x.x + x.y * x.y + x.z * x.z + x.w * x.w;
        #pragma unroll
        for (int m = 16; m >= 1; m >>= 1) ss += __shfl_xor_sync(0xffffffffu, ss, m);
        float inv = 1.f / fmaxf(sqrtf(ss), 1e-12f);
        x.x *= inv; x.y *= inv; x.z *= inv; x.w *= inv;
        ((float4*)g_ent)[w * 32 + lane] = x;
        agg4[w * 32 + lane] = make_float4(0.f, 0.f, 0.f, 0.f);
    } else {
        int r = w - N_ENTv;
        if (r >= KG_LEAFv) return;
        float4* usr4 = (float4*)g_usr;
        float4* agg4 = (float4*)g_usragg;
        float4* res4 = (float4*)g_usrres;
        const float4* lat4 = (const float4*)latent;
        const float4* dw4 = (const float4*)g_dw;

        float4 u = usr4[r * 32 + lane];   // OLD user_emb for score
        float l[8];
        #pragma unroll
        for (int k = 0; k < 8; k++) {
            float4 lt = lat4[k * 32 + lane];
            float p = u.x * lt.x + u.y * lt.y + u.z * lt.z + u.w * lt.w;
            #pragma unroll
            for (int m = 16; m >= 1; m >>= 1) p += __shfl_xor_sync(0xffffffffu, p, m);
            l[k] = p;
        }
        float mx = l[0];
        #pragma unroll
        for (int k = 1; k < 8; k++) mx = fmaxf(mx, l[k]);
        float s = 0.f;
        #pragma unroll
        for (int k = 0; k < 8; k++) { l[k] = __expf(l[k] - mx); s += l[k]; }
        float invs = 1.f / s;
        float4 g = make_float4(0.f, 0.f, 0.f, 0.f);
        #pragma unroll
        for (int k = 0; k < 8; k++) {
            float sc = l[k] * invs;
            float4 d = dw4[k * 32 + lane];
            g.x += sc * d.x; g.y += sc * d.y; g.z += sc * d.z; g.w += sc * d.w;
        }
        float4 a = agg4[r * 32 + lane];
        a.x *= (1.f + g.x); a.y *= (1.f + g.y); a.z *= (1.f + g.z); a.w *= (1.f + g.w);
        float ss = a.x * a.x + a.y * a.y + a.z * a.z + a.w * a.w;
        #pragma unroll
        for (int m = 16; m >= 1; m >>= 1) ss += __shfl_xor_sync(0xffffffffu, ss, m);
        float inv = 1.f / fmaxf(sqrtf(ss), 1e-12f);
        a.x *= inv; a.y *= inv; a.z *= inv; a.w *= inv;
        usr4[r * 32 + lane] = a;
        float4 rr = res4[r * 32 + lane];
        rr.x += a.x; rr.y += a.y; rr.z += a.z; rr.w += a.w;
        res4[r * 32 + lane] = rr;
        agg4[r * 32 + lane] = make_float4(0.f, 0.f, 0.f, 0.f);
    }
}

// ---------------- build distinct-code matrices X, IK; zero P -----------------
__global__ void k_buildX(const float* __restrict__ dt, const float* __restrict__ pt,
                         const float* __restrict__ mt) {
    int i = blockIdx.x * blockDim.x + threadIdx.x;
    if (i >= MROWSv * Cv) return;
    int row = i >> 7, c = i & 127;
    float x;
    if (row < V0v)             x = dt[row * Cv + c];
    else if (row < V0v + V1v)  x = pt[(row - V0v) * Cv + c];
    else                       x = mt[(row - V0v - V1v) * Cv + c];
    g_X[i] = x;
    g_IK[i] = (row < KG_LEAFv) ? g_usrres[i] : 0.f;
    g_P[i] = 0.f;
}

// ---------------- GEMM A: E = exp(X @ L^T), g_s = rowsum(E) ------------------
__global__ void __launch_bounds__(256) kA_logits() {
    __shared__ float Xs[32][132];
    __shared__ float Ls[32][132];
    const int rowbase = blockIdx.x * 128;
    const int colbase = blockIdx.y * 128;
    const int t = threadIdx.x;
    const int tx = t & 15, ty = t >> 4;
    const int m0 = ty * 8, n0 = tx * 8;
    float acc[8][8];
    #pragma unroll
    for (int i = 0; i < 8; i++)
        #pragma unroll
        for (int j = 0; j < 8; j++) acc[i][j] = 0.f;

    for (int kc = 0; kc < 4; kc++) {
        #pragma unroll
        for (int it = 0; it < 4; it++) {
            int lin = t + it * 256;
            int row = lin >> 3, q = lin & 7;
            int gr = rowbase + row;
            float4 v = make_float4(0.f, 0.f, 0.f, 0.f);
            if (gr < MROWSv) v = *(const float4*)&g_X[gr * Cv + kc * 32 + q * 4];
            Xs[q * 4 + 0][row] = v.x; Xs[q * 4 + 1][row] = v.y;
            Xs[q * 4 + 2][row] = v.z; Xs[q * 4 + 3][row] = v.w;
            int gc = colbase + row;
            float4 w = make_float4(0.f, 0.f, 0.f, 0.f);
            if (gc < KG_LEAFv) w = *(const float4*)&g_usrres[gc * Cv + kc * 32 + q * 4];
            Ls[q * 4 + 0][row] = w.x; Ls[q * 4 + 1][row] = w.y;
            Ls[q * 4 + 2][row] = w.z; Ls[q * 4 + 3][row] = w.w;
        }
        __syncthreads();
        #pragma unroll
        for (int kk = 0; kk < 32; kk++) {
            float4 a0 = *(const float4*)&Xs[kk][m0];
            float4 a1 = *(const float4*)&Xs[kk][m0 + 4];
            float4 b0 = *(const float4*)&Ls[kk][n0];
            float4 b1 = *(const float4*)&Ls[kk][n0 + 4];
            float a[8] = {a0.x, a0.y, a0.z, a0.w, a1.x, a1.y, a1.z, a1.w};
            float b[8] = {b0.x, b0.y, b0.z, b0.w, b1.x, b1.y, b1.z, b1.w};
            #pragma unroll
            for (int i = 0; i < 8; i++)
                #pragma unroll
                for (int j = 0; j < 8; j++) acc[i][j] += a[i] * b[j];
        }
        __syncthreads();
    }
    #pragma unroll
    for (int i = 0; i < 8; i++) {
        int row = rowbase + m0 + i;
        float rs = 0.f;
        if (row < MROWSv) {
            #pragma unroll
            for (int j = 0; j < 8; j++) {
                int col = colbase + n0 + j;
                if (col < KG_LEAFv) {
                    float e = __expf(acc[i][j]);
                    g_E[row * LDEv + col] = e;
                    rs += e;
                }
            }
        }
        rs += __shfl_xor_sync(0xffffffffu, rs, 1);
        rs += __shfl_xor_sync(0xffffffffu, rs, 2);
        rs += __shfl_xor_sync(0xffffffffu, rs, 4);
        rs += __shfl_xor_sync(0xffffffffu, rs, 8);
        if (tx == 0 && row < MROWSv) atomicAdd(&g_s[row], rs);
    }
}

// ---------------- GEMM B: g_P += (E @ L) — split-K, atomic partials ----------
// grid (28 row tiles, KSPLIT). Each split handles 11 of 110 K-chunks of 32.
__global__ void __launch_bounds__(256) kB_P() {
    __shared__ float Es[32][132];
    __shared__ float Ls[32][132];
    const int rowbase = blockIdx.x * 128;
    const int ch0 = blockIdx.y * 11;
    const int t = threadIdx.x;
    const int tx = t & 15, ty = t >> 4;
    const int m0 = ty * 8, n0 = tx * 8;
    float acc[8][8];
    #pragma unroll
    for (int i = 0; i < 8; i++)
        #pragma unroll
        for (int j = 0; j < 8; j++) acc[i][j] = 0.f;

    for (int ch = ch0; ch < ch0 + 11; ch++) {
        int j0 = ch * 32;
        #pragma unroll
        for (int it = 0; it < 4; it++) {
            int lin = t + it * 256;
            int row = lin >> 3, q = lin & 7;
            int gr = rowbase + row;
            int k = j0 + q * 4;
            float4 v = make_float4(0.f, 0.f, 0.f, 0.f);
            if (gr < MROWSv) {
                if (k + 3 < KG_LEAFv) {
                    v = *(const float4*)&g_E[gr * LDEv + k];
                } else {
                    float* vp = &v.x;
                    #pragma unroll
                    for (int j = 0; j < 4; j++)
                        if (k + j < KG_LEAFv) vp[j] = g_E[gr * LDEv + k + j];
                }
            }
            Es[q * 4 + 0][row] = v.x; Es[q * 4 + 1][row] = v.y;
            Es[q * 4 + 2][row] = v.z; Es[q * 4 + 3][row] = v.w;
        }
        #pragma unroll
        for (int it = 0; it < 4; it++) {
            int lin = t + it * 256;
            int kr = lin >> 5, q = lin & 31;
            int gk = j0 + kr;
            float4 v = make_float4(0.f, 0.f, 0.f, 0.f);
            if (gk < KG_LEAFv) v = *(const float4*)&g_usrres[gk * Cv + q * 4];
            *(float4*)&Ls[kr][q * 4] = v;
        }
        __syncthreads();
        #pragma unroll
        for (int kk = 0; kk < 32; kk++) {
            float4 a0 = *(const float4*)&Es[kk][m0];
            float4 a1 = *(const float4*)&Es[kk][m0 + 4];
            float4 b0 = *(const float4*)&Ls[kk][n0];
            float4 b1 = *(const float4*)&Ls[kk][n0 + 4];
            float a[8] = {a0.x, a0.y, a0.z, a0.w, a1.x, a1.y, a1.z, a1.w};
            float b[8] = {b0.x, b0.y, b0.z, b0.w, b1.x, b1.y, b1.z, b1.w};
            #pragma unroll
            for (int i = 0; i < 8; i++)
                #pragma unroll
                for (int j = 0; j < 8; j++) acc[i][j] += a[i] * b[j];
        }
        __syncthreads();
    }
    #pragma unroll
    for (int i = 0; i < 8; i++) {
        int row = rowbase + m0 + i;
        if (row < MROWSv) {
            atomAdd4((float4*)&g_P[row * Cv + n0],
                     make_float4(acc[i][0], acc[i][1], acc[i][2], acc[i][3]));
            atomAdd4((float4*)&g_P[row * Cv + n0 + 4],
                     make_float4(acc[i][4], acc[i][5], acc[i][6], acc[i][7]));
        }
    }
}

// ---------------- tanh tables (normalizes P by rowsum here) ------------------
__global__ void __launch_bounds__(128) k_tanh(
        const float* __restrict__ dw_, const float* __restrict__ db_,
        const float* __restrict__ pw_, const float* __restrict__ pb_,
        const float* __restrict__ mw_, const float* __restrict__ mb_) {
    int row = blockIdx.x;
    int c = threadIdx.x;
    __shared__ float sIn[256];
    float invs = 1.f / g_s[row];
    sIn[c] = g_P[row * Cv + c] * invs;
    sIn[128 + c] = g_IK[row * Cv + c];
    __syncthreads();
    const float* W; const float* b;
    if (row < V0v)            { W = dw_; b = db_; }
    else if (row < V0v + V1v) { W = pw_; b = pb_; }
    else                      { W = mw_; b = mb_; }
    float au = 0.f, am = 0.f;
    #pragma unroll 4
    for (int r = 0; r < 128; r++) au += sIn[r] * W[r * Cv + c];
    #pragma unroll 4
    for (int r = 128; r < 256; r++) {
        float v = sIn[r] * W[r * Cv + c];
        au += v; am += v;
    }
    g_Tun[row * Cv + c] = tanhf(au + b[c]);
    g_Tma[row * Cv + c] = tanhf(am + b[c]);
}

// ---------------- final: per-(b,s) gather-sum + 384->128 matvec + tanh -------
__global__ void __launch_bounds__(128) k_final(
        const int* __restrict__ dis, const int* __restrict__ prc,
        const int* __restrict__ med,
        const float* __restrict__ dm, const float* __restrict__ pm,
        const float* __restrict__ mm,
        const float* __restrict__ cw, const float* __restrict__ cb,
        float* __restrict__ out) {
    int bs = blockIdx.x;           // b*S + s, 0..127
    int s = bs & (Sv - 1);
    int c = threadIdx.x;
    __shared__ float cat[384];
    float ad = 0.f, ap = 0.f, am = 0.f;
    for (int n = 0; n < NDv; n++) {
        int idx = dis[bs * NDv + n];
        bool msk = dm[bs * NDv + n] != 0.f;
        ad += msk ? g_Tma[idx * Cv + c] : g_Tun[idx * Cv + c];
    }
    for (int n = 0; n < NPv; n++) {
        int idx = prc[bs * NPv + n] + V0v;
        bool msk = pm[bs * NPv + n] != 0.f;
        ap += msk ? g_Tma[idx * Cv + c] : g_Tun[idx * Cv + c];
    }
    if (s == 0) {
        am = (float)NMv * g_Tma[(MROWSv - 1) * Cv + c];  // MED_PAD code, masked
    } else {
        int pb = bs - 1;
        for (int n = 0; n < NMv; n++) {
            int idx = med[pb * NMv + n] + (V0v + V1v);
            bool msk = mm[pb * NMv + n] != 0.f;
            am += msk ? g_Tma[idx * Cv + c] : g_Tun[idx * Cv + c];
        }
    }
    cat[c] = ad; cat[128 + c] = ap; cat[256 + c] = am;
    __syncthreads();
    float acc = cb[c];
    #pragma unroll 4
    for (int r = 0; r < 384; r++) acc += cat[r] * cw[r * Cv + c];
    out[bs * Cv + c] = tanhf(acc);
}

// ---------------- launch -----------------------------------------------------
extern "C" void kernel_launch(void* const* d_in, const int* in_sizes, int n_in,
                              void* d_out, int out_size) {
    const int*   diseases    = (const int*)  d_in[0];
    const int*   procedures  = (const int*)  d_in[1];
    const int*   medications = (const int*)  d_in[2];
    const float* d_mask      = (const float*)d_in[3];
    const float* p_mask      = (const float*)d_in[4];
    const float* m_mask      = (const float*)d_in[5];
    const int*   edge_head   = (const int*)  d_in[6];
    const int*   edge_tail   = (const int*)  d_in[7];
    const int*   edge_type   = (const int*)  d_in[8];
    const int*   inter_rows  = (const int*)  d_in[9];
    const int*   inter_cols  = (const int*)  d_in[10];
    const float* inter_vals  = (const float*)d_in[11];
    const float* all_embed   = (const float*)d_in[12];
    const float* latent_emb  = (const float*)d_in[13];
    const float* kg_weight   = (const float*)d_in[14];
    const float* disen_att   = (const float*)d_in[15];
    const float* diag_table  = (const float*)d_in[16];
    const float* proc_table  = (const float*)d_in[17];
    const float* med_table   = (const float*)d_in[18];
    const float* diag_w      = (const float*)d_in[19];
    const float* diag_b      = (const float*)d_in[20];
    const float* proc_w      = (const float*)d_in[21];
    const float* proc_b      = (const float*)d_in[22];
    const float* med_w       = (const float*)d_in[23];
    const float* med_b       = (const float*)d_in[24];
    const float* curt_w      = (const float*)d_in[25];
    const float* curt_b      = (const float*)d_in[26];
    float* out = (float*)d_out;

    k_init<<<(N_ENTv * Cv + 255) / 256, 256>>>(all_embed);
    k_disen<<<1, 128>>>(disen_att, kg_weight);

    const int scatterWarps = E_KGv + NNZv;
    const int updateWarps  = N_ENTv + KG_LEAFv;
    for (int h = 0; h < 3; h++) {
        k_scatter<<<(scatterWarps + 7) / 8, 256>>>(edge_head, edge_tail, edge_type,
                                                   kg_weight, inter_rows, inter_cols,
                                                   inter_vals);
        k_update<<<(updateWarps + 7) / 8, 256>>>(latent_emb);
    }

    k_buildX<<<(MROWSv * Cv + 255) / 256, 256>>>(diag_table, proc_table, med_table);

    dim3 gA(28, 28);
    kA_logits<<<gA, 256>>>();
    dim3 gB(28, KSPLITv);
    kB_P<<<gB, 256>>>();

    k_tanh<<<MROWSv, 128>>>(diag_w, diag_b, proc_w, proc_b, med_w, med_b);
    k_final<<<Bv * Sv, 128>>>(diseases, procedures, medications,
                              d_mask, p_mask, m_mask, curt_w, curt_b, out);
}

// round 5
// speedup vs baseline: 1.9515x; 1.1782x over previous
#include <cuda_runtime.h>
#include <math.h>

// ---------------- problem constants ----------------
#define V0v 1958
#define V1v 1430
#define V2v 131
#define KG_LEAFv 3519
#define N_ENTv 96481
#define Cv 128
#define E_KGv 500000
#define NNZv 200000
#define MROWSv 3522            // 1958 diag + 1430 proc + 134 med rows
#define LDEv 3520              // leading dim of E (padded to /32)
#define Bv 16
#define Sv 8
#define NDv 40
#define NPv 30
#define NMv 30
#define KSPLITv 10             // split-K factor for GEMM B

// ---------------- device scratch (static globals: no runtime allocation) ----
// NOTE: .bss is zero-initialized at module load. g_entagg / g_usragg are
// restored to zero by k_update every hop, so they are never re-zeroed here.
__device__ __align__(16) float g_ent[N_ENTv * Cv];      // entity_emb (current)
__device__ __align__(16) float g_entagg[N_ENTv * Cv];   // edge scatter target
__device__ __align__(16) float g_usr[KG_LEAFv * Cv];    // user_emb (current)
__device__ __align__(16) float g_usragg[KG_LEAFv * Cv];
__device__ __align__(16) float g_usrres[KG_LEAFv * Cv]; // leaf_intent accumulator
__device__ __align__(16) float g_dw[8 * Cv];            // disen_weight (8,128)
__device__ __align__(16) float g_X[MROWSv * Cv];        // distinct code embeddings
__device__ __align__(16) float g_IK[MROWSv * Cv];       // per-code ik vectors
__device__ __align__(16) float g_E[MROWSv * LDEv];      // exp(logits) ~49.6MB
__device__ __align__(16) float g_P[MROWSv * Cv];        // E@L partial sums (unnormalized)
__device__ float g_s[MROWSv];                           // row sums of E
__device__ __align__(16) float g_Tun[MROWSv * Cv];      // tanh table, unmasked
__device__ __align__(16) float g_Tma[MROWSv * Cv];      // tanh table, masked (int=0)

__device__ __forceinline__ void atomAdd4(float4* addr, float4 v) {
#if defined(__CUDA_ARCH__) && (__CUDA_ARCH__ >= 900)
    atomicAdd(addr, v);
#else
    float* a = (float*)addr;
    atomicAdd(a + 0, v.x); atomicAdd(a + 1, v.y);
    atomicAdd(a + 2, v.z); atomicAdd(a + 3, v.w);
#endif
}

// ---- packed f32x2 helpers (sm_100+: 2x FMA issue rate via fma.rn.f32x2) ----
__device__ __forceinline__ unsigned long long pack2(float x, float y) {
    unsigned long long r;
    asm("mov.b64 %0, {%1, %2};" : "=l"(r) : "f"(x), "f"(y));
    return r;
}
__device__ __forceinline__ float2 unpack2(unsigned long long v) {
    float2 r;
    asm("mov.b64 {%0, %1}, %2;" : "=f"(r.x), "=f"(r.y) : "l"(v));
    return r;
}
__device__ __forceinline__ unsigned long long ffma2(
        unsigned long long a, unsigned long long b, unsigned long long c) {
    unsigned long long d;
    asm("fma.rn.f32x2 %0, %1, %2, %3;" : "=l"(d) : "l"(a), "l"(b), "l"(c));
    return d;
}

// ---------------- init: copy embeddings (agg buffers stay zero by invariant) -
__global__ void k_init(const float* __restrict__ all_embed) {
    int i = blockIdx.x * blockDim.x + threadIdx.x;
    if (i < KG_LEAFv * Cv) {
        float v = all_embed[i];
        g_usr[i] = v; g_usrres[i] = v;
    }
    if (i < N_ENTv * Cv) {
        g_ent[i] = all_embed[KG_LEAFv * Cv + i];
    }
    if (i < MROWSv) g_s[i] = 0.f;
}

// ---------------- disen_weight = softmax(disen_att, -1) @ kg_weight ----------
__global__ void k_disen(const float* __restrict__ att, const float* __restrict__ kw) {
    __shared__ float p[8 * 49];
    int t = threadIdx.x;
    if (t < 8) {
        float m = -1e30f;
        for (int r = 0; r < 49; r++) m = fmaxf(m, att[t * 49 + r]);
        float s = 0.f;
        for (int r = 0; r < 49; r++) { float e = __expf(att[t * 49 + r] - m); p[t * 49 + r] = e; s += e; }
        float inv = 1.f / s;
        for (int r = 0; r < 49; r++) p[t * 49 + r] *= inv;
    }
    __syncthreads();
    for (int k = 0; k < 8; k++) {
        float a = 0.f;
        for (int r = 0; r < 49; r++) a += p[k * 49 + r] * kw[r * Cv + t];
        g_dw[k * Cv + t] = a;
    }
}

// ---------------- GNN hop: merged scatter, 4 items per warp (MLP=4) ----------
// warps [0, E_KG/4): 4 edges each; warps [E_KG/4, E_KG/4+NNZ/4): 4 nnz each.
#define EWARPSv (E_KGv / 4)
#define IWARPSv (NNZv / 4)
__global__ void __launch_bounds__(256) k_scatter(
        const int* __restrict__ eh, const int* __restrict__ et,
        const int* __restrict__ ety, const float* __restrict__ kw,
        const int* __restrict__ ir, const int* __restrict__ ic,
        const float* __restrict__ iv) {
    int gid = blockIdx.x * blockDim.x + threadIdx.x;
    int w = gid >> 5, lane = gid & 31;
    if (w < EWARPSv) {
        int base = w * 4;
        int tl[4], ty[4], hh[4];
        #pragma unroll
        for (int i = 0; i < 4; i++) {
            tl[i] = et[base + i]; ty[i] = ety[base + i]; hh[i] = eh[base + i];
        }
        float4 v[4];
        #pragma unroll
        for (int i = 0; i < 4; i++) v[i] = ((const float4*)g_ent)[tl[i] * 32 + lane];
        float4 ww[4];
        #pragma unroll
        for (int i = 0; i < 4; i++) ww[i] = ((const float4*)kw)[(ty[i] - 1) * 32 + lane];
        #pragma unroll
        for (int i = 0; i < 4; i++) {
            v[i].x *= ww[i].x; v[i].y *= ww[i].y; v[i].z *= ww[i].z; v[i].w *= ww[i].w;
            atomAdd4(((float4*)g_entagg) + hh[i] * 32 + lane, v[i]);
        }
    } else {
        int q = w - EWARPSv;
        if (q >= IWARPSv) return;
        int base = q * 4;
        int rr[4], cc[4];
        float vv[4];
        #pragma unroll
        for (int i = 0; i < 4; i++) {
            rr[i] = ir[base + i]; cc[i] = ic[base + i]; vv[i] = iv[base + i];
        }
        float4 x[4];
        #pragma unroll
        for (int i = 0; i < 4; i++) x[i] = ((const float4*)g_ent)[cc[i] * 32 + lane];
        #pragma unroll
        for (int i = 0; i < 4; i++) {
            x[i].x *= vv[i]; x[i].y *= vv[i]; x[i].z *= vv[i]; x[i].w *= vv[i];
            atomAdd4(((float4*)g_usragg) + rr[i] * 32 + lane, x[i]);
        }
    }
}

// ---------------- GNN hop: merged entity + user update -----------------------
__global__ void __launch_bounds__(256) k_update(const float* __restrict__ latent) {
    int gid = blockIdx.x * blockDim.x + threadIdx.x;
    int w = gid >> 5, lane = gid & 31;
    if (w < N_ENTv) {
        float4* agg4 = (float4*)g_entagg;
        float4 x = agg4[w * 32 + lane];
        float ss = x.x * x.x + x.y * x.y + x.z * x.z + x.w * x.w;
        #pragma unroll
        for (int m = 16; m >= 1; m >>= 1) ss += __shfl_xor_sync(0xffffffffu, ss, m);
        float inv = 1.f / fmaxf(sqrtf(ss), 1e-12f);
        x.x *= inv; x.y *= inv; x.z *= inv; x.w *= inv;
        ((float4*)g_ent)[w * 32 + lane] = x;
        agg4[w * 32 + lane] = make_float4(0.f, 0.f, 0.f, 0.f);
    } else {
        int r = w - N_ENTv;
        if (r >= KG_LEAFv) return;
        float4* usr4 = (float4*)g_usr;
        float4* agg4 = (float4*)g_usragg;
        float4* res4 = (float4*)g_usrres;
        const float4* lat4 = (const float4*)latent;
        const float4* dw4 = (const float4*)g_dw;

        float4 u = usr4[r * 32 + lane];   // OLD user_emb for score
        float l[8];
        #pragma unroll
        for (int k = 0; k < 8; k++) {
            float4 lt = lat4[k * 32 + lane];
            float p = u.x * lt.x + u.y * lt.y + u.z * lt.z + u.w * lt.w;
            #pragma unroll
            for (int m = 16; m >= 1; m >>= 1) p += __shfl_xor_sync(0xffffffffu, p, m);
            l[k] = p;
        }
        float mx = l[0];
        #pragma unroll
        for (int k = 1; k < 8; k++) mx = fmaxf(mx, l[k]);
        float s = 0.f;
        #pragma unroll
        for (int k = 0; k < 8; k++) { l[k] = __expf(l[k] - mx); s += l[k]; }
        float invs = 1.f / s;
        float4 g = make_float4(0.f, 0.f, 0.f, 0.f);
        #pragma unroll
        for (int k = 0; k < 8; k++) {
            float sc = l[k] * invs;
            float4 d = dw4[k * 32 + lane];
            g.x += sc * d.x; g.y += sc * d.y; g.z += sc * d.z; g.w += sc * d.w;
        }
        float4 a = agg4[r * 32 + lane];
        a.x *= (1.f + g.x); a.y *= (1.f + g.y); a.z *= (1.f + g.z); a.w *= (1.f + g.w);
        float ss = a.x * a.x + a.y * a.y + a.z * a.z + a.w * a.w;
        #pragma unroll
        for (int m = 16; m >= 1; m >>= 1) ss += __shfl_xor_sync(0xffffffffu, ss, m);
        float inv = 1.f / fmaxf(sqrtf(ss), 1e-12f);
        a.x *= inv; a.y *= inv; a.z *= inv; a.w *= inv;
        usr4[r * 32 + lane] = a;
        float4 rr = res4[r * 32 + lane];
        rr.x += a.x; rr.y += a.y; rr.z += a.z; rr.w += a.w;
        res4[r * 32 + lane] = rr;
        agg4[r * 32 + lane] = make_float4(0.f, 0.f, 0.f, 0.f);
    }
}

// ---------------- build distinct-code matrices X, IK; zero P -----------------
__global__ void k_buildX(const float* __restrict__ dt, const float* __restrict__ pt,
                         const float* __restrict__ mt) {
    int i = blockIdx.x * blockDim.x + threadIdx.x;
    if (i >= MROWSv * Cv) return;
    int row = i >> 7, c = i & 127;
    float x;
    if (row < V0v)             x = dt[row * Cv + c];
    else if (row < V0v + V1v)  x = pt[(row - V0v) * Cv + c];
    else                       x = mt[(row - V0v - V1v) * Cv + c];
    g_X[i] = x;
    g_IK[i] = (row < KG_LEAFv) ? g_usrres[i] : 0.f;
    g_P[i] = 0.f;
}

// ---------------- GEMM A: E = exp(X @ L^T), g_s = rowsum(E) ------------------
// 128x128 tiles, 256 threads, 8x8 microtile via packed f32x2 FMA.
__global__ void __launch_bounds__(256) kA_logits() {
    __shared__ float Xs[32][132];
    __shared__ float Ls[32][132];
    const int rowbase = blockIdx.x * 128;
    const int colbase = blockIdx.y * 128;
    const int t = threadIdx.x;
    const int tx = t & 15, ty = t >> 4;
    const int m0 = ty * 8, n0 = tx * 8;
    unsigned long long acc[8][4];
    #pragma unroll
    for (int i = 0; i < 8; i++)
        #pragma unroll
        for (int j = 0; j < 4; j++) acc[i][j] = 0ull;

    for (int kc = 0; kc < 4; kc++) {
        #pragma unroll
        for (int it = 0; it < 4; it++) {
            int lin = t + it * 256;
            int row = lin >> 3, q = lin & 7;
            int gr = rowbase + row;
            float4 v = make_float4(0.f, 0.f, 0.f, 0.f);
            if (gr < MROWSv) v = *(const float4*)&g_X[gr * Cv + kc * 32 + q * 4];
            Xs[q * 4 + 0][row] = v.x; Xs[q * 4 + 1][row] = v.y;
            Xs[q * 4 + 2][row] = v.z; Xs[q * 4 + 3][row] = v.w;
            int gc = colbase + row;
            float4 w = make_float4(0.f, 0.f, 0.f, 0.f);
            if (gc < KG_LEAFv) w = *(const float4*)&g_usrres[gc * Cv + kc * 32 + q * 4];
            Ls[q * 4 + 0][row] = w.x; Ls[q * 4 + 1][row] = w.y;
            Ls[q * 4 + 2][row] = w.z; Ls[q * 4 + 3][row] = w.w;
        }
        __syncthreads();
        #pragma unroll
        for (int kk = 0; kk < 32; kk++) {
            float4 a0 = *(const float4*)&Xs[kk][m0];
            float4 a1 = *(const float4*)&Xs[kk][m0 + 4];
            ulonglong2 bp0 = *(const ulonglong2*)&Ls[kk][n0];
            ulonglong2 bp1 = *(const ulonglong2*)&Ls[kk][n0 + 4];
            unsigned long long bb[4] = {bp0.x, bp0.y, bp1.x, bp1.y};
            float a[8] = {a0.x, a0.y, a0.z, a0.w, a1.x, a1.y, a1.z, a1.w};
            #pragma unroll
            for (int i = 0; i < 8; i++) {
                unsigned long long aa = pack2(a[i], a[i]);
                #pragma unroll
                for (int j = 0; j < 4; j++) acc[i][j] = ffma2(aa, bb[j], acc[i][j]);
            }
        }
        __syncthreads();
    }
    #pragma unroll
    for (int i = 0; i < 8; i++) {
        int row = rowbase + m0 + i;
        float rs = 0.f;
        if (row < MROWSv) {
            #pragma unroll
            for (int j = 0; j < 4; j++) {
                float2 z = unpack2(acc[i][j]);
                int col = colbase + n0 + 2 * j;
                if (col < KG_LEAFv) {
                    float e = __expf(z.x);
                    g_E[row * LDEv + col] = e;
                    rs += e;
                }
                if (col + 1 < KG_LEAFv) {
                    float e = __expf(z.y);
                    g_E[row * LDEv + col + 1] = e;
                    rs += e;
                }
            }
        }
        rs += __shfl_xor_sync(0xffffffffu, rs, 1);
        rs += __shfl_xor_sync(0xffffffffu, rs, 2);
        rs += __shfl_xor_sync(0xffffffffu, rs, 4);
        rs += __shfl_xor_sync(0xffffffffu, rs, 8);
        if (tx == 0 && row < MROWSv) atomicAdd(&g_s[row], rs);
    }
}

// ---------------- GEMM B: g_P += (E @ L) — split-K, f32x2, atomic partials ---
__global__ void __launch_bounds__(256) kB_P() {
    __shared__ float Es[32][132];
    __shared__ float Ls[32][132];
    const int rowbase = blockIdx.x * 128;
    const int ch0 = blockIdx.y * 11;
    const int t = threadIdx.x;
    const int tx = t & 15, ty = t >> 4;
    const int m0 = ty * 8, n0 = tx * 8;
    unsigned long long acc[8][4];
    #pragma unroll
    for (int i = 0; i < 8; i++)
        #pragma unroll
        for (int j = 0; j < 4; j++) acc[i][j] = 0ull;

    for (int ch = ch0; ch < ch0 + 11; ch++) {
        int j0 = ch * 32;
        #pragma unroll
        for (int it = 0; it < 4; it++) {
            int lin = t + it * 256;
            int row = lin >> 3, q = lin & 7;
            int gr = rowbase + row;
            int k = j0 + q * 4;
            float4 v = make_float4(0.f, 0.f, 0.f, 0.f);
            if (gr < MROWSv) {
                if (k + 3 < KG_LEAFv) {
                    v = *(const float4*)&g_E[gr * LDEv + k];
                } else {
                    float* vp = &v.x;
                    #pragma unroll
                    for (int j = 0; j < 4; j++)
                        if (k + j < KG_LEAFv) vp[j] = g_E[gr * LDEv + k + j];
                }
            }
            Es[q * 4 + 0][row] = v.x; Es[q * 4 + 1][row] = v.y;
            Es[q * 4 + 2][row] = v.z; Es[q * 4 + 3][row] = v.w;
        }
        #pragma unroll
        for (int it = 0; it < 4; it++) {
            int lin = t + it * 256;
            int kr = lin >> 5, q = lin & 31;
            int gk = j0 + kr;
            float4 v = make_float4(0.f, 0.f, 0.f, 0.f);
            if (gk < KG_LEAFv) v = *(const float4*)&g_usrres[gk * Cv + q * 4];
            *(float4*)&Ls[kr][q * 4] = v;
        }
        __syncthreads();
        #pragma unroll
        for (int kk = 0; kk < 32; kk++) {
            float4 a0 = *(const float4*)&Es[kk][m0];
            float4 a1 = *(const float4*)&Es[kk][m0 + 4];
            ulonglong2 bp0 = *(const ulonglong2*)&Ls[kk][n0];
            ulonglong2 bp1 = *(const ulonglong2*)&Ls[kk][n0 + 4];
            unsigned long long bb[4] = {bp0.x, bp0.y, bp1.x, bp1.y};
            float a[8] = {a0.x, a0.y, a0.z, a0.w, a1.x, a1.y, a1.z, a1.w};
            #pragma unroll
            for (int i = 0; i < 8; i++) {
                unsigned long long aa = pack2(a[i], a[i]);
                #pragma unroll
                for (int j = 0; j < 4; j++) acc[i][j] = ffma2(aa, bb[j], acc[i][j]);
            }
        }
        __syncthreads();
    }
    #pragma unroll
    for (int i = 0; i < 8; i++) {
        int row = rowbase + m0 + i;
        if (row < MROWSv) {
            float2 p0 = unpack2(acc[i][0]);
            float2 p1 = unpack2(acc[i][1]);
            float2 p2 = unpack2(acc[i][2]);
            float2 p3 = unpack2(acc[i][3]);
            atomAdd4((float4*)&g_P[row * Cv + n0],
                     make_float4(p0.x, p0.y, p1.x, p1.y));
            atomAdd4((float4*)&g_P[row * Cv + n0 + 4],
                     make_float4(p2.x, p2.y, p3.x, p3.y));
        }
    }
}

// ---------------- tanh tables: 8 rows per block, W value reused 8x -----------
__global__ void __launch_bounds__(128) k_tanh(
        const float* __restrict__ dw_, const float* __restrict__ db_,
        const float* __restrict__ pw_, const float* __restrict__ pb_,
        const float* __restrict__ mw_, const float* __restrict__ mb_) {
    const int base = blockIdx.x * 8;
    const int c = threadIdx.x;
    __shared__ float sP[8][128];
    __shared__ float sIK[8][128];
    #pragma unroll
    for (int rr = 0; rr < 8; rr++) {
        int row = base + rr;
        if (row < MROWSv) {
            sP[rr][c] = g_P[row * Cv + c] * (1.f / g_s[row]);
            sIK[rr][c] = g_IK[row * Cv + c];
        } else {
            sP[rr][c] = 0.f; sIK[rr][c] = 0.f;
        }
    }
    __syncthreads();
    int lastrow = min(base + 7, MROWSv - 1);
    int cat0 = base < V0v ? 0 : (base < V0v + V1v ? 1 : 2);
    int cat1 = lastrow < V0v ? 0 : (lastrow < V0v + V1v ? 1 : 2);
    if (cat0 == cat1) {
        const float* W = cat0 == 0 ? dw_ : (cat0 == 1 ? pw_ : mw_);
        const float* b = cat0 == 0 ? db_ : (cat0 == 1 ? pb_ : mb_);
        float au[8] = {0,0,0,0,0,0,0,0}, am[8] = {0,0,0,0,0,0,0,0};
        for (int r = 0; r < 128; r++) {
            float w = W[r * Cv + c];
            #pragma unroll
            for (int rr = 0; rr < 8; rr++) au[rr] += sP[rr][r] * w;
        }
        for (int r = 0; r < 128; r++) {
            float w = W[(128 + r) * Cv + c];
            #pragma unroll
            for (int rr = 0; rr < 8; rr++) {
                float v = sIK[rr][r] * w;
                au[rr] += v; am[rr] += v;
            }
        }
        float bc = b[c];
        #pragma unroll
        for (int rr = 0; rr < 8; rr++) {
            int row = base + rr;
            if (row < MROWSv) {
                g_Tun[row * Cv + c] = tanhf(au[rr] + bc);
                g_Tma[row * Cv + c] = tanhf(am[rr] + bc);
            }
        }
    } else {
        // straddles a category boundary (only 2 of 441 blocks): per-row path
        for (int rr = 0; rr < 8; rr++) {
            int row = base + rr;
            if (row >= MROWSv) break;
            const float* W = row < V0v ? dw_ : (row < V0v + V1v ? pw_ : mw_);
            const float* b = row < V0v ? db_ : (row < V0v + V1v ? pb_ : mb_);
            float au = 0.f, am = 0.f;
            for (int r = 0; r < 128; r++) au += sP[rr][r] * W[r * Cv + c];
            for (int r = 0; r < 128; r++) {
                float v = sIK[rr][r] * W[(128 + r) * Cv + c];
                au += v; am += v;
            }
            g_Tun[row * Cv + c] = tanhf(au + b[c]);
            g_Tma[row * Cv + c] = tanhf(am + b[c]);
        }
    }
}

// ---------------- final: per-(b,s) gather-sum + 384->128 matvec + tanh -------
__global__ void __launch_bounds__(128) k_final(
        const int* __restrict__ dis, const int* __restrict__ prc,
        const int* __restrict__ med,
        const float* __restrict__ dm, const float* __restrict__ pm,
        const float* __restrict__ mm,
        const float* __restrict__ cw, const float* __restrict__ cb,
        float* __restrict__ out) {
    int bs = blockIdx.x;           // b*S + s, 0..127
    int s = bs & (Sv - 1);
    int c = threadIdx.x;
    __shared__ float cat[384];
    float ad = 0.f, ap = 0.f, am = 0.f;
    for (int n = 0; n < NDv; n++) {
        int idx = dis[bs * NDv + n];
        bool msk = dm[bs * NDv + n] != 0.f;
        ad += msk ? g_Tma[idx * Cv + c] : g_Tun[idx * Cv + c];
    }
    for (int n = 0; n < NPv; n++) {
        int idx = prc[bs * NPv + n] + V0v;
        bool msk = pm[bs * NPv + n] != 0.f;
        ap += msk ? g_Tma[idx * Cv + c] : g_Tun[idx * Cv + c];
    }
    if (s == 0) {
        am = (float)NMv * g_Tma[(MROWSv - 1) * Cv + c];  // MED_PAD code, masked
    } else {
        int pb = bs - 1;
        for (int n = 0; n < NMv; n++) {
            int idx = med[pb * NMv + n] + (V0v + V1v);
            bool msk = mm[pb * NMv + n] != 0.f;
            am += msk ? g_Tma[idx * Cv + c] : g_Tun[idx * Cv + c];
        }
    }
    cat[c] = ad; cat[128 + c] = ap; cat[256 + c] = am;
    __syncthreads();
    float acc = cb[c];
    #pragma unroll 4
    for (int r = 0; r < 384; r++) acc += cat[r] * cw[r * Cv + c];
    out[bs * Cv + c] = tanhf(acc);
}

// ---------------- launch -----------------------------------------------------
extern "C" void kernel_launch(void* const* d_in, const int* in_sizes, int n_in,
                              void* d_out, int out_size) {
    const int*   diseases    = (const int*)  d_in[0];
    const int*   procedures  = (const int*)  d_in[1];
    const int*   medications = (const int*)  d_in[2];
    const float* d_mask      = (const float*)d_in[3];
    const float* p_mask      = (const float*)d_in[4];
    const float* m_mask      = (const float*)d_in[5];
    const int*   edge_head   = (const int*)  d_in[6];
    const int*   edge_tail   = (const int*)  d_in[7];
    const int*   edge_type   = (const int*)  d_in[8];
    const int*   inter_rows  = (const int*)  d_in[9];
    const int*   inter_cols  = (const int*)  d_in[10];
    const float* inter_vals  = (const float*)d_in[11];
    const float* all_embed   = (const float*)d_in[12];
    const float* latent_emb  = (const float*)d_in[13];
    const float* kg_weight   = (const float*)d_in[14];
    const float* disen_att   = (const float*)d_in[15];
    const float* diag_table  = (const float*)d_in[16];
    const float* proc_table  = (const float*)d_in[17];
    const float* med_table   = (const float*)d_in[18];
    const float* diag_w      = (const float*)d_in[19];
    const float* diag_b      = (const float*)d_in[20];
    const float* proc_w      = (const float*)d_in[21];
    const float* proc_b      = (const float*)d_in[22];
    const float* med_w       = (const float*)d_in[23];
    const float* med_b       = (const float*)d_in[24];
    const float* curt_w      = (const float*)d_in[25];
    const float* curt_b      = (const float*)d_in[26];
    float* out = (float*)d_out;

    k_init<<<(N_ENTv * Cv + 255) / 256, 256>>>(all_embed);
    k_disen<<<1, 128>>>(disen_att, kg_weight);

    const int scatterWarps = EWARPSv + IWARPSv;   // 175000 warps
    const int updateWarps  = N_ENTv + KG_LEAFv;
    for (int h = 0; h < 3; h++) {
        k_scatter<<<(scatterWarps + 7) / 8, 256>>>(edge_head, edge_tail, edge_type,
                                                   kg_weight, inter_rows, inter_cols,
                                                   inter_vals);
        k_update<<<(updateWarps + 7) / 8, 256>>>(latent_emb);
    }

    k_buildX<<<(MROWSv * Cv + 255) / 256, 256>>>(diag_table, proc_table, med_table);

    dim3 gA(28, 28);
    kA_logits<<<gA, 256>>>();
    dim3 gB(28, KSPLITv);
    kB_P<<<gB, 256>>>();

    k_tanh<<<(MROWSv + 7) / 8, 128>>>(diag_w, diag_b, proc_w, proc_b, med_w, med_b);
    k_final<<<Bv * Sv, 128>>>(diseases, procedures, medications,
                              d_mask, p_mask, m_mask, curt_w, curt_b, out);
}